// round 2
// baseline (speedup 1.0000x reference)
#include <cuda_runtime.h>
#include <math.h>

#define DIM 768
#define HEADS 12
#define HEAD_DIM 64
#define BATCH 4
#define SEQ 2048
#define QKV_DIM (3 * DIM)
#define SCALE 0.125f  // 64^-0.5

// Scratch (no allocations allowed): qkv activations + attention output
__device__ float g_qkv[(size_t)BATCH * SEQ * QKV_DIM];  // [B,N,2304] = 75.5 MB
__device__ float g_att[(size_t)BATCH * SEQ * DIM];      // [B,N,768]  = 25.2 MB

// ---------------------------------------------------------------------------
// SGEMM (NT): C[M,N] = A[M,K] * B[N,K]^T + bias[N]
// 128x128 tile, BK=8, 256 threads, 8x8 per-thread microtile.
// ---------------------------------------------------------------------------
#define BM 128
#define BN 128
#define BK 8

__global__ __launch_bounds__(256) void sgemm_nt_bias(
    const float* __restrict__ A, const float* __restrict__ B,
    const float* __restrict__ bias, float* __restrict__ C,
    int M, int N, int K) {
    __shared__ float As[BK][BM + 4];
    __shared__ float Bs[BK][BN + 4];

    const int bx = blockIdx.x;  // N tile
    const int by = blockIdx.y;  // M tile
    const int tid = threadIdx.x;

    // Global-load mapping: each thread loads one float4 of A and one of B per K-step
    const int lrow = tid >> 1;          // 0..127
    const int lcol = (tid & 1) * 4;     // 0 or 4

    const float* Aptr = A + (size_t)(by * BM + lrow) * K + lcol;
    const float* Bptr = B + (size_t)(bx * BN + lrow) * K + lcol;

    const int tx = tid & 15;   // 0..15 -> 8 output cols each
    const int ty = tid >> 4;   // 0..15 -> 8 output rows each

    float acc[8][8];
#pragma unroll
    for (int i = 0; i < 8; i++)
#pragma unroll
        for (int j = 0; j < 8; j++) acc[i][j] = 0.f;

    for (int k0 = 0; k0 < K; k0 += BK) {
        float4 a4 = *(const float4*)Aptr;  Aptr += BK;
        float4 b4 = *(const float4*)Bptr;  Bptr += BK;
        As[lcol + 0][lrow] = a4.x; As[lcol + 1][lrow] = a4.y;
        As[lcol + 2][lrow] = a4.z; As[lcol + 3][lrow] = a4.w;
        Bs[lcol + 0][lrow] = b4.x; Bs[lcol + 1][lrow] = b4.y;
        Bs[lcol + 2][lrow] = b4.z; Bs[lcol + 3][lrow] = b4.w;
        __syncthreads();

#pragma unroll
        for (int k = 0; k < BK; k++) {
            float4 a0 = *(const float4*)&As[k][ty * 8];
            float4 a1 = *(const float4*)&As[k][ty * 8 + 4];
            float4 b0 = *(const float4*)&Bs[k][tx * 8];
            float4 b1 = *(const float4*)&Bs[k][tx * 8 + 4];
            float ar[8] = {a0.x, a0.y, a0.z, a0.w, a1.x, a1.y, a1.z, a1.w};
            float br[8] = {b0.x, b0.y, b0.z, b0.w, b1.x, b1.y, b1.z, b1.w};
#pragma unroll
            for (int i = 0; i < 8; i++)
#pragma unroll
                for (int j = 0; j < 8; j++) acc[i][j] = fmaf(ar[i], br[j], acc[i][j]);
        }
        __syncthreads();
    }

    // Epilogue: add bias, vectorized stores
    const int col0 = bx * BN + tx * 8;
    float bv[8];
#pragma unroll
    for (int j = 0; j < 8; j++) bv[j] = __ldg(&bias[col0 + j]);

#pragma unroll
    for (int i = 0; i < 8; i++) {
        const int row = by * BM + ty * 8 + i;
        float4 c0, c1;
        c0.x = acc[i][0] + bv[0]; c0.y = acc[i][1] + bv[1];
        c0.z = acc[i][2] + bv[2]; c0.w = acc[i][3] + bv[3];
        c1.x = acc[i][4] + bv[4]; c1.y = acc[i][5] + bv[5];
        c1.z = acc[i][6] + bv[6]; c1.w = acc[i][7] + bv[7];
        *(float4*)&C[(size_t)row * N + col0]     = c0;
        *(float4*)&C[(size_t)row * N + col0 + 4] = c1;
    }
}

// ---------------------------------------------------------------------------
// Flash attention (fp32, online softmax). One thread per q row.
// Br=128 rows/CTA (128 threads), Bc=64 K/V tile in smem.
// grid = (SEQ/128, HEADS, BATCH)
// q row, o accumulator, scores all register-resident; K/V smem reads are
// warp-uniform (broadcast) -> conflict-free.
// ---------------------------------------------------------------------------
#define FA_BR 128
#define FA_BC 64

__global__ __launch_bounds__(FA_BR) void flash_attn_fp32(
    const float* __restrict__ qkv, float* __restrict__ out) {
    const int qt = blockIdx.x;
    const int h  = blockIdx.y;
    const int b  = blockIdx.z;
    const int r  = threadIdx.x;  // 0..127

    __shared__ float ks[FA_BC][HEAD_DIM];
    __shared__ float vs[FA_BC][HEAD_DIM];

    const size_t base = (size_t)b * SEQ * QKV_DIM;
    const float* qptr = qkv + base + (size_t)(qt * FA_BR + r) * QKV_DIM + h * HEAD_DIM;

    float q[HEAD_DIM];
#pragma unroll
    for (int d4 = 0; d4 < 16; d4++) {
        float4 t = *(const float4*)(qptr + d4 * 4);
        q[d4 * 4 + 0] = t.x; q[d4 * 4 + 1] = t.y;
        q[d4 * 4 + 2] = t.z; q[d4 * 4 + 3] = t.w;
    }

    float o[HEAD_DIM];
#pragma unroll
    for (int d = 0; d < HEAD_DIM; d++) o[d] = 0.f;
    float mrow = -1e30f;
    float lsum = 0.f;

    const int jrow = r >> 1;             // K/V tile row this thread loads
    const int doff = (r & 1) * 32;       // which half of the 64-dim row

    for (int kt = 0; kt < SEQ / FA_BC; kt++) {
        // Cooperative K/V tile load: 64 rows x 64 floats each
        const float* kg = qkv + base + (size_t)(kt * FA_BC + jrow) * QKV_DIM
                          + DIM + h * HEAD_DIM + doff;
        const float* vg = kg + DIM;
#pragma unroll
        for (int i = 0; i < 8; i++) {
            *(float4*)&ks[jrow][doff + i * 4] = *(const float4*)(kg + i * 4);
            *(float4*)&vs[jrow][doff + i * 4] = *(const float4*)(vg + i * 4);
        }
        __syncthreads();

#pragma unroll
        for (int jc = 0; jc < FA_BC / 16; jc++) {
            float s[16];
#pragma unroll
            for (int jj = 0; jj < 16; jj++) {
                const int j = jc * 16 + jj;
                float a = 0.f;
#pragma unroll
                for (int d4 = 0; d4 < 16; d4++) {
                    float4 kv = *(const float4*)&ks[j][d4 * 4];
                    a = fmaf(q[d4 * 4 + 0], kv.x, a);
                    a = fmaf(q[d4 * 4 + 1], kv.y, a);
                    a = fmaf(q[d4 * 4 + 2], kv.z, a);
                    a = fmaf(q[d4 * 4 + 3], kv.w, a);
                }
                s[jj] = a * SCALE;
            }
            float mnew = mrow;
#pragma unroll
            for (int jj = 0; jj < 16; jj++) mnew = fmaxf(mnew, s[jj]);
            const float corr = __expf(mrow - mnew);
            mrow = mnew;
            lsum *= corr;
#pragma unroll
            for (int d = 0; d < HEAD_DIM; d++) o[d] *= corr;
#pragma unroll
            for (int jj = 0; jj < 16; jj++) {
                const int j = jc * 16 + jj;
                const float p = __expf(s[jj] - mrow);
                lsum += p;
#pragma unroll
                for (int d4 = 0; d4 < 16; d4++) {
                    float4 vv = *(const float4*)&vs[j][d4 * 4];
                    o[d4 * 4 + 0] = fmaf(p, vv.x, o[d4 * 4 + 0]);
                    o[d4 * 4 + 1] = fmaf(p, vv.y, o[d4 * 4 + 1]);
                    o[d4 * 4 + 2] = fmaf(p, vv.z, o[d4 * 4 + 2]);
                    o[d4 * 4 + 3] = fmaf(p, vv.w, o[d4 * 4 + 3]);
                }
            }
        }
        __syncthreads();
    }

    const float inv = 1.f / lsum;
    float* optr = out + ((size_t)b * SEQ + qt * FA_BR + r) * DIM + h * HEAD_DIM;
#pragma unroll
    for (int d4 = 0; d4 < 16; d4++) {
        float4 t;
        t.x = o[d4 * 4 + 0] * inv; t.y = o[d4 * 4 + 1] * inv;
        t.z = o[d4 * 4 + 2] * inv; t.w = o[d4 * 4 + 3] * inv;
        *(float4*)(optr + d4 * 4) = t;
    }
}

// ---------------------------------------------------------------------------
extern "C" void kernel_launch(void* const* d_in, const int* in_sizes, int n_in,
                              void* d_out, int out_size) {
    const float* x      = (const float*)d_in[0];
    const float* w_qkv  = (const float*)d_in[1];
    const float* b_qkv  = (const float*)d_in[2];
    const float* w_proj = (const float*)d_in[3];
    const float* b_proj = (const float*)d_in[4];
    float* out = (float*)d_out;

    float* qkv = nullptr;
    float* att = nullptr;
    cudaGetSymbolAddress((void**)&qkv, g_qkv);
    cudaGetSymbolAddress((void**)&att, g_att);

    const int M = BATCH * SEQ;  // 8192

    // 1) QKV projection: [8192,768] x [2304,768]^T -> [8192,2304]
    {
        dim3 grid(QKV_DIM / BN, M / BM);  // (18, 64)
        sgemm_nt_bias<<<grid, 256>>>(x, w_qkv, b_qkv, qkv, M, QKV_DIM, DIM);
    }

    // 2) Flash attention per (b, h): -> g_att [B,N,768]
    {
        dim3 grid(SEQ / FA_BR, HEADS, BATCH);  // (16, 12, 4)
        flash_attn_fp32<<<grid, FA_BR>>>(qkv, att);
    }

    // 3) Output projection: [8192,768] x [768,768]^T -> d_out
    {
        dim3 grid(DIM / BN, M / BM);  // (6, 64)
        sgemm_nt_bias<<<grid, 256>>>(att, w_proj, b_proj, out, M, DIM, DIM);
    }
}

// round 3
// speedup vs baseline: 4.0512x; 4.0512x over previous
#include <cuda_runtime.h>
#include <math.h>

#define DIM 768
#define HEADS 12
#define HEAD_DIM 64
#define BATCH 4
#define SEQ 2048
#define QKV_DIM (3 * DIM)
#define SCALE 0.125f

__device__ float g_qkv[(size_t)BATCH * SEQ * QKV_DIM];
__device__ float g_att[(size_t)BATCH * SEQ * DIM];

__device__ __forceinline__ unsigned f2tf32(float x) {
    unsigned u;
    asm("cvt.rna.tf32.f32 %0, %1;" : "=r"(u) : "f"(x));
    return u;
}

__device__ __forceinline__ void mma_tf32(float c[4], const unsigned a[4],
                                         unsigned b0, unsigned b1) {
    asm volatile(
        "mma.sync.aligned.m16n8k8.row.col.f32.tf32.tf32.f32 "
        "{%0,%1,%2,%3}, {%4,%5,%6,%7}, {%8,%9}, {%0,%1,%2,%3};"
        : "+f"(c[0]), "+f"(c[1]), "+f"(c[2]), "+f"(c[3])
        : "r"(a[0]), "r"(a[1]), "r"(a[2]), "r"(a[3]), "r"(b0), "r"(b1));
}

// ---------------------------------------------------------------------------
// TF32 GEMM (NT): C[M,N] = A[M,K]*B[N,K]^T + bias. 128x128 tile, BK=16,
// 256 threads = 8 warps (4m x 2n), warp tile 32x64.
// smem stored k-major with stride 132 (== 4 mod 32 -> conflict-free frags).
// ---------------------------------------------------------------------------
__global__ __launch_bounds__(256) void gemm_tf32_nt_bias(
    const float* __restrict__ A, const float* __restrict__ B,
    const float* __restrict__ bias, float* __restrict__ C,
    int M, int N, int K) {
    __shared__ unsigned As[16][132];
    __shared__ unsigned Bs[16][132];

    const int tid = threadIdx.x;
    const int lane = tid & 31;
    const int wid = tid >> 5;
    const int wm = wid & 3;          // 0..3
    const int wn = wid >> 2;         // 0..1
    const int bx = blockIdx.x, by = blockIdx.y;

    const int lr = tid >> 1;         // 0..127
    const int lc = (tid & 1) * 8;    // 0 or 8
    const float* Ag = A + (size_t)(by * 128 + lr) * K + lc;
    const float* Bg = B + (size_t)(bx * 128 + lr) * K + lc;

    float acc[2][8][4];
#pragma unroll
    for (int i = 0; i < 2; i++)
#pragma unroll
        for (int j = 0; j < 8; j++)
#pragma unroll
            for (int e = 0; e < 4; e++) acc[i][j][e] = 0.f;

    for (int k0 = 0; k0 < K; k0 += 16) {
        float4 a0 = *(const float4*)Ag;
        float4 a1 = *(const float4*)(Ag + 4);
        float4 b0 = *(const float4*)Bg;
        float4 b1 = *(const float4*)(Bg + 4);
        Ag += 16; Bg += 16;
        As[lc + 0][lr] = f2tf32(a0.x); As[lc + 1][lr] = f2tf32(a0.y);
        As[lc + 2][lr] = f2tf32(a0.z); As[lc + 3][lr] = f2tf32(a0.w);
        As[lc + 4][lr] = f2tf32(a1.x); As[lc + 5][lr] = f2tf32(a1.y);
        As[lc + 6][lr] = f2tf32(a1.z); As[lc + 7][lr] = f2tf32(a1.w);
        Bs[lc + 0][lr] = f2tf32(b0.x); Bs[lc + 1][lr] = f2tf32(b0.y);
        Bs[lc + 2][lr] = f2tf32(b0.z); Bs[lc + 3][lr] = f2tf32(b0.w);
        Bs[lc + 4][lr] = f2tf32(b1.x); Bs[lc + 5][lr] = f2tf32(b1.y);
        Bs[lc + 6][lr] = f2tf32(b1.z); Bs[lc + 7][lr] = f2tf32(b1.w);
        __syncthreads();

#pragma unroll
        for (int kc = 0; kc < 2; kc++) {
            const int k = kc * 8 + (lane & 3);
            unsigned af[2][4];
#pragma unroll
            for (int mt = 0; mt < 2; mt++) {
                const int m = wm * 32 + mt * 16 + (lane >> 2);
                af[mt][0] = As[k][m];
                af[mt][1] = As[k][m + 8];
                af[mt][2] = As[k + 4][m];
                af[mt][3] = As[k + 4][m + 8];
            }
#pragma unroll
            for (int nt = 0; nt < 8; nt++) {
                const int n = wn * 64 + nt * 8 + (lane >> 2);
                const unsigned bf0 = Bs[k][n];
                const unsigned bf1 = Bs[k + 4][n];
#pragma unroll
                for (int mt = 0; mt < 2; mt++)
                    mma_tf32(acc[mt][nt], af[mt], bf0, bf1);
            }
        }
        __syncthreads();
    }

    // epilogue
#pragma unroll
    for (int nt = 0; nt < 8; nt++) {
        const int col = bx * 128 + wn * 64 + nt * 8 + 2 * (lane & 3);
        const float bv0 = __ldg(&bias[col]);
        const float bv1 = __ldg(&bias[col + 1]);
#pragma unroll
        for (int mt = 0; mt < 2; mt++) {
            const int row = by * 128 + wm * 32 + mt * 16 + (lane >> 2);
            float2 v0 = make_float2(acc[mt][nt][0] + bv0, acc[mt][nt][1] + bv1);
            float2 v1 = make_float2(acc[mt][nt][2] + bv0, acc[mt][nt][3] + bv1);
            *(float2*)&C[(size_t)row * N + col] = v0;
            *(float2*)&C[(size_t)(row + 8) * N + col] = v1;
        }
    }
}

// ---------------------------------------------------------------------------
// TF32 flash attention. CTA = 128 q-rows of one (b,h); 8 warps, 16 rows/warp.
// KV tiles of 64 keys in smem (stride 68 -> conflict-free B frags).
// P goes through per-warp smem buffer to re-fragment for the PV mma.
// ---------------------------------------------------------------------------
#define FB_BC 64
#define KV_STRIDE 68

extern __shared__ unsigned fa_smem[];

__global__ __launch_bounds__(256) void flash_tf32(
    const float* __restrict__ qkv, float* __restrict__ out) {
    unsigned* ks = fa_smem;                       // [64][68]
    unsigned* vs = ks + 64 * KV_STRIDE;           // [64][68]
    unsigned* pbAll = vs + 64 * KV_STRIDE;        // [8][16][68]

    const int tid = threadIdx.x;
    const int lane = tid & 31;
    const int wid = tid >> 5;
    const int qt = blockIdx.x, h = blockIdx.y, b = blockIdx.z;
    unsigned* pb = pbAll + wid * 16 * KV_STRIDE;

    const size_t base = (size_t)b * SEQ * QKV_DIM;
    const int r0g = qt * 128 + wid * 16 + (lane >> 2);   // global q row (low)

    // Q fragments (scale folded in; exact since SCALE = 2^-3)
    unsigned qa[8][4];
    {
        const float* q0 = qkv + base + (size_t)r0g * QKV_DIM + h * HEAD_DIM + (lane & 3);
        const float* q1 = q0 + (size_t)8 * QKV_DIM;
#pragma unroll
        for (int kc = 0; kc < 8; kc++) {
            qa[kc][0] = f2tf32(q0[kc * 8] * SCALE);
            qa[kc][1] = f2tf32(q1[kc * 8] * SCALE);
            qa[kc][2] = f2tf32(q0[kc * 8 + 4] * SCALE);
            qa[kc][3] = f2tf32(q1[kc * 8 + 4] * SCALE);
        }
    }

    float o[8][4];
#pragma unroll
    for (int nc = 0; nc < 8; nc++)
#pragma unroll
        for (int e = 0; e < 4; e++) o[nc][e] = 0.f;
    float m0 = -1e30f, m1 = -1e30f, l0 = 0.f, l1 = 0.f;

    const int ldr = tid >> 2;            // KV row this thread loads (0..63)
    const int ldc = (tid & 3) * 16;      // 16-float segment

    for (int kt = 0; kt < SEQ / FB_BC; kt++) {
        // cooperative K/V tile load + tf32 convert
        const float* kg = qkv + base + (size_t)(kt * FB_BC + ldr) * QKV_DIM
                          + DIM + h * HEAD_DIM + ldc;
        const float* vg = kg + DIM;
#pragma unroll
        for (int i = 0; i < 4; i++) {
            float4 kv4 = *(const float4*)(kg + i * 4);
            float4 vv4 = *(const float4*)(vg + i * 4);
            unsigned* kd = ks + ldr * KV_STRIDE + ldc + i * 4;
            unsigned* vd = vs + ldr * KV_STRIDE + ldc + i * 4;
            kd[0] = f2tf32(kv4.x); kd[1] = f2tf32(kv4.y);
            kd[2] = f2tf32(kv4.z); kd[3] = f2tf32(kv4.w);
            vd[0] = f2tf32(vv4.x); vd[1] = f2tf32(vv4.y);
            vd[2] = f2tf32(vv4.z); vd[3] = f2tf32(vv4.w);
        }
        __syncthreads();

        // S = Q * K^T  (16 x 64 per warp)
        float sc[8][4];
#pragma unroll
        for (int nc = 0; nc < 8; nc++) {
#pragma unroll
            for (int e = 0; e < 4; e++) sc[nc][e] = 0.f;
            const int key = nc * 8 + (lane >> 2);
#pragma unroll
            for (int kc = 0; kc < 8; kc++) {
                const unsigned bf0 = ks[key * KV_STRIDE + kc * 8 + (lane & 3)];
                const unsigned bf1 = ks[key * KV_STRIDE + kc * 8 + (lane & 3) + 4];
                mma_tf32(sc[nc], qa[kc], bf0, bf1);
            }
        }

        // online softmax (rows r0 = lane/4, r1 = r0+8; quad shares the row)
        float t0 = -1e30f, t1 = -1e30f;
#pragma unroll
        for (int nc = 0; nc < 8; nc++) {
            t0 = fmaxf(t0, fmaxf(sc[nc][0], sc[nc][1]));
            t1 = fmaxf(t1, fmaxf(sc[nc][2], sc[nc][3]));
        }
        t0 = fmaxf(t0, __shfl_xor_sync(0xffffffffu, t0, 1));
        t0 = fmaxf(t0, __shfl_xor_sync(0xffffffffu, t0, 2));
        t1 = fmaxf(t1, __shfl_xor_sync(0xffffffffu, t1, 1));
        t1 = fmaxf(t1, __shfl_xor_sync(0xffffffffu, t1, 2));
        const float mn0 = fmaxf(m0, t0);
        const float mn1 = fmaxf(m1, t1);
        const float corr0 = __expf(m0 - mn0);
        const float corr1 = __expf(m1 - mn1);
        m0 = mn0; m1 = mn1;
        l0 *= corr0; l1 *= corr1;
#pragma unroll
        for (int nc = 0; nc < 8; nc++) {
            o[nc][0] *= corr0; o[nc][1] *= corr0;
            o[nc][2] *= corr1; o[nc][3] *= corr1;
            float p0 = __expf(sc[nc][0] - m0);
            float p1 = __expf(sc[nc][1] - m0);
            float p2 = __expf(sc[nc][2] - m1);
            float p3 = __expf(sc[nc][3] - m1);
            l0 += p0 + p1; l1 += p2 + p3;
            const int col = nc * 8 + 2 * (lane & 3);
            unsigned* pr0 = pb + (lane >> 2) * KV_STRIDE + col;
            unsigned* pr1 = pr0 + 8 * KV_STRIDE;
            pr0[0] = f2tf32(p0); pr0[1] = f2tf32(p1);
            pr1[0] = f2tf32(p2); pr1[1] = f2tf32(p3);
        }
        __syncwarp();

        // O += P * V   (P: 16 x 64 keys, V: 64 keys x 64 dims)
#pragma unroll
        for (int kc = 0; kc < 8; kc++) {
            unsigned af[4];
            const unsigned* pr = pb + (lane >> 2) * KV_STRIDE + kc * 8 + (lane & 3);
            af[0] = pr[0];
            af[1] = pr[8 * KV_STRIDE];
            af[2] = pr[4];
            af[3] = pr[8 * KV_STRIDE + 4];
            const int keyr = (kc * 8 + (lane & 3)) * KV_STRIDE;
#pragma unroll
            for (int nc = 0; nc < 8; nc++) {
                const int dcol = nc * 8 + (lane >> 2);
                const unsigned bf0 = vs[keyr + dcol];
                const unsigned bf1 = vs[keyr + 4 * KV_STRIDE + dcol];
                mma_tf32(o[nc], af, bf0, bf1);
            }
        }
        __syncthreads();
    }

    l0 += __shfl_xor_sync(0xffffffffu, l0, 1);
    l0 += __shfl_xor_sync(0xffffffffu, l0, 2);
    l1 += __shfl_xor_sync(0xffffffffu, l1, 1);
    l1 += __shfl_xor_sync(0xffffffffu, l1, 2);
    const float inv0 = 1.f / l0;
    const float inv1 = 1.f / l1;

    float* o0 = out + ((size_t)b * SEQ + r0g) * DIM + h * HEAD_DIM;
    float* o1 = o0 + (size_t)8 * DIM;
#pragma unroll
    for (int nc = 0; nc < 8; nc++) {
        const int col = nc * 8 + 2 * (lane & 3);
        *(float2*)(o0 + col) = make_float2(o[nc][0] * inv0, o[nc][1] * inv0);
        *(float2*)(o1 + col) = make_float2(o[nc][2] * inv1, o[nc][3] * inv1);
    }
}

// ---------------------------------------------------------------------------
extern "C" void kernel_launch(void* const* d_in, const int* in_sizes, int n_in,
                              void* d_out, int out_size) {
    const float* x      = (const float*)d_in[0];
    const float* w_qkv  = (const float*)d_in[1];
    const float* b_qkv  = (const float*)d_in[2];
    const float* w_proj = (const float*)d_in[3];
    const float* b_proj = (const float*)d_in[4];
    float* out = (float*)d_out;

    float* qkv = nullptr;
    float* att = nullptr;
    cudaGetSymbolAddress((void**)&qkv, g_qkv);
    cudaGetSymbolAddress((void**)&att, g_att);

    const int M = BATCH * SEQ;  // 8192
    const int FA_SMEM = (64 * KV_STRIDE * 2 + 8 * 16 * KV_STRIDE) * 4;  // 69632

    cudaFuncSetAttribute(flash_tf32, cudaFuncAttributeMaxDynamicSharedMemorySize,
                         FA_SMEM);

    {
        dim3 grid(QKV_DIM / 128, M / 128);  // (18, 64)
        gemm_tf32_nt_bias<<<grid, 256>>>(x, w_qkv, b_qkv, qkv, M, QKV_DIM, DIM);
    }
    {
        dim3 grid(SEQ / 128, HEADS, BATCH);  // (16, 12, 4)
        flash_tf32<<<grid, 256, FA_SMEM>>>(qkv, att);
    }
    {
        dim3 grid(DIM / 128, M / 128);  // (6, 64)
        gemm_tf32_nt_bias<<<grid, 256>>>(att, w_proj, b_proj, out, M, DIM, DIM);
    }
}

// round 5
// speedup vs baseline: 4.9955x; 1.2331x over previous
#include <cuda_runtime.h>
#include <math.h>

#define DIM 768
#define HEADS 12
#define HEAD_DIM 64
#define BATCH 4
#define SEQ 2048
#define QKV_DIM (3 * DIM)
#define QSCALE 0.18033688011112042f  /* 0.125 * log2(e) */

__device__ float g_qkv[(size_t)BATCH * SEQ * QKV_DIM];
__device__ float g_att[(size_t)BATCH * SEQ * DIM];

__device__ __forceinline__ unsigned f2tf32(float x) {
    unsigned u;
    asm("cvt.rna.tf32.f32 %0, %1;" : "=r"(u) : "f"(x));
    return u;
}
__device__ __forceinline__ float ex2(float x) {
    float y;
    asm("ex2.approx.f32 %0, %1;" : "=f"(y) : "f"(x));
    return y;
}
__device__ __forceinline__ void mma_tf32(float c[4], const unsigned a[4],
                                         unsigned b0, unsigned b1) {
    asm volatile(
        "mma.sync.aligned.m16n8k8.row.col.f32.tf32.tf32.f32 "
        "{%0,%1,%2,%3}, {%4,%5,%6,%7}, {%8,%9}, {%0,%1,%2,%3};"
        : "+f"(c[0]), "+f"(c[1]), "+f"(c[2]), "+f"(c[3])
        : "r"(a[0]), "r"(a[1]), "r"(a[2]), "r"(a[3]), "r"(b0), "r"(b1));
}

// ===========================================================================
// TF32 GEMM (NT) v3: C = A[M,K]*B[N,K]^T + bias. 128x128 tile, BK=16,
// 128 threads = 4 warps (2m x 2n), warp tile 64x64 (mt=4, nt=8).
// Pair-packed smem: A pairs (m,m+8) -> LDS.64; B pairs (k,k+4) -> LDS.64.
// Double-buffered smem with register prefetch; one sync per k-tile.
// ===========================================================================
#define GSA 136                      // A smem k-row stride (words), 136%32==8
#define GSB 40                       // B smem n-row stride (words), 40%32==8
#define G_ASIZE (16 * GSA)           // 2176 words
#define G_BSIZE (128 * GSB)          // 5120 words
#define G_BUF (G_ASIZE + G_BSIZE)    // 7296 words per buffer

extern __shared__ unsigned dyn_smem[];

__global__ __launch_bounds__(128) void gemm_tf32_v3(
    const float* __restrict__ A, const float* __restrict__ B,
    const float* __restrict__ bias, float* __restrict__ C,
    int M, int N, int K) {
    const int tid = threadIdx.x;
    const int lane = tid & 31;
    const int wid = tid >> 5;
    const int wm = wid & 1, wn = wid >> 1;
    const int bx = blockIdx.x, by = blockIdx.y;
    const int r0 = lane >> 2, q4 = lane & 3;

    // A loader: thread -> row-pair (m, m+8), 8 k-values
    const int ap = tid >> 1;             // 0..63
    const int ag = ap >> 3, ar = ap & 7; // m = ag*16+ar (+8)
    const int ak = (tid & 1) * 8;        // k-offset 0 or 8
    const float* Ag = A + (size_t)(by * 128 + ag * 16 + ar) * K + ak;
    // B loader: thread -> row n, 16 k-values
    const float* Bg = B + (size_t)(bx * 128 + tid) * K;

    float4 u0, u1, v0, v1, w0, w1, w2, w3;
    u0 = *(const float4*)Ag;             u1 = *(const float4*)(Ag + 4);
    v0 = *(const float4*)(Ag + 8 * K);   v1 = *(const float4*)(Ag + 8 * K + 4);
    w0 = *(const float4*)Bg;             w1 = *(const float4*)(Bg + 4);
    w2 = *(const float4*)(Bg + 8);       w3 = *(const float4*)(Bg + 12);

    float acc[4][8][4];
#pragma unroll
    for (int i = 0; i < 4; i++)
#pragma unroll
        for (int j = 0; j < 8; j++)
#pragma unroll
            for (int e = 0; e < 4; e++) acc[i][j][e] = 0.f;

    const int jA = ag * 16 + ar * 2;

    // store tile (from regs) into buffer s
    auto store_tile = [&](unsigned* s) {
        unsigned* As = s;
        unsigned* Bs = s + G_ASIZE;
        float ua[8] = {u0.x, u0.y, u0.z, u0.w, u1.x, u1.y, u1.z, u1.w};
        float va[8] = {v0.x, v0.y, v0.z, v0.w, v1.x, v1.y, v1.z, v1.w};
#pragma unroll
        for (int i = 0; i < 8; i++) {
            uint2 t;
            t.x = f2tf32(ua[i]);
            t.y = f2tf32(va[i]);
            *(uint2*)&As[(ak + i) * GSA + jA] = t;
        }
        float fb[16] = {w0.x, w0.y, w0.z, w0.w, w1.x, w1.y, w1.z, w1.w,
                        w2.x, w2.y, w2.z, w2.w, w3.x, w3.y, w3.z, w3.w};
#pragma unroll
        for (int kb = 0; kb < 2; kb++)
#pragma unroll
            for (int qq = 0; qq < 4; qq++) {
                uint2 t;
                t.x = f2tf32(fb[kb * 8 + qq]);
                t.y = f2tf32(fb[kb * 8 + qq + 4]);
                *(uint2*)&Bs[tid * GSB + kb * 8 + qq * 2] = t;
            }
    };

    store_tile(dyn_smem);
    __syncthreads();

    const int NT = K / 16;
    for (int t = 0; t < NT; t++) {
        if (t + 1 < NT) {
            Ag += 16; Bg += 16;
            u0 = *(const float4*)Ag;           u1 = *(const float4*)(Ag + 4);
            v0 = *(const float4*)(Ag + 8 * K); v1 = *(const float4*)(Ag + 8 * K + 4);
            w0 = *(const float4*)Bg;           w1 = *(const float4*)(Bg + 4);
            w2 = *(const float4*)(Bg + 8);     w3 = *(const float4*)(Bg + 12);
        }
        {
            const unsigned* As = dyn_smem + (t & 1) * G_BUF;
            const unsigned* Bs = As + G_ASIZE;
#pragma unroll
            for (int kc = 0; kc < 2; kc++) {
                const int kr = kc * 8 + q4;
                unsigned af[4][4];
#pragma unroll
                for (int mt = 0; mt < 4; mt++) {
                    const int j = (wm * 4 + mt) * 16 + r0 * 2;
                    uint2 p0 = *(const uint2*)&As[kr * GSA + j];
                    uint2 p1 = *(const uint2*)&As[(kr + 4) * GSA + j];
                    af[mt][0] = p0.x; af[mt][1] = p0.y;
                    af[mt][2] = p1.x; af[mt][3] = p1.y;
                }
#pragma unroll
                for (int nt = 0; nt < 8; nt++) {
                    const int n = wn * 64 + nt * 8 + r0;
                    uint2 bb = *(const uint2*)&Bs[n * GSB + kc * 8 + q4 * 2];
#pragma unroll
                    for (int mt = 0; mt < 4; mt++)
                        mma_tf32(acc[mt][nt], af[mt], bb.x, bb.y);
                }
            }
        }
        if (t + 1 < NT) store_tile(dyn_smem + ((t + 1) & 1) * G_BUF);
        __syncthreads();
    }

    // epilogue
#pragma unroll
    for (int nt = 0; nt < 8; nt++) {
        const int col = bx * 128 + wn * 64 + nt * 8 + 2 * q4;
        const float bv0 = __ldg(&bias[col]);
        const float bv1 = __ldg(&bias[col + 1]);
#pragma unroll
        for (int mt = 0; mt < 4; mt++) {
            const int row = by * 128 + wm * 64 + mt * 16 + r0;
            *(float2*)&C[(size_t)row * N + col] =
                make_float2(acc[mt][nt][0] + bv0, acc[mt][nt][1] + bv1);
            *(float2*)&C[(size_t)(row + 8) * N + col] =
                make_float2(acc[mt][nt][2] + bv0, acc[mt][nt][3] + bv1);
        }
    }
}

// ===========================================================================
// TF32 flash attention v3. CTA = 128 threads (4 warps), 128 q-rows
// (warp tile 32x64: mt=2). KV tile = 64 keys. Pair-packed smem:
//   ks2[key][kb*8+q*2+e]  = K[key][kb*8+q+4e]          (LDS.64 B-frags)
//   vp [dcol][kb*8+q*2+e] = V[kb*8+q+4e][dcol]         (LDS.64 B-frags)
//   pp [w][mt*8+r][col*2+e] = P[mt*16+r+8e][col]       (STS.128 / LDS.64)
// Softmax in exp2 domain (log2e folded into Q scale).
// ===========================================================================
#define KS 72                          // 72%32==8
#define PS 136                         // 136%32==8
#define F_V (64 * KS)                  // 4608 words
#define F_P (2 * 64 * KS)              // 9216 words
#define F_WORDS (F_P + 8 * 8 * PS)     // 17920 words = 71680 B

__global__ __launch_bounds__(128) void flash_tf32_v3(
    const float* __restrict__ qkv, float* __restrict__ out) {
    unsigned* ks2 = dyn_smem;
    unsigned* vp = dyn_smem + F_V;

    const int tid = threadIdx.x;
    const int lane = tid & 31;
    const int wid = tid >> 5;           // 0..3
    const int r0 = lane >> 2, q4 = lane & 3;
    const int qt = blockIdx.x, h = blockIdx.y, b = blockIdx.z;
    unsigned* pw = dyn_smem + F_P + wid * (2 * 8 * PS);

    const size_t base = (size_t)b * SEQ * QKV_DIM;

    // Q fragments, scale*log2e folded
    unsigned qa[2][8][4];
#pragma unroll
    for (int mt = 0; mt < 2; mt++) {
        const int row = qt * 128 + wid * 32 + mt * 16 + r0;
        const float* p0 = qkv + base + (size_t)row * QKV_DIM + h * HEAD_DIM + q4;
        const float* p1 = p0 + (size_t)8 * QKV_DIM;
#pragma unroll
        for (int kc = 0; kc < 8; kc++) {
            qa[mt][kc][0] = f2tf32(p0[kc * 8] * QSCALE);
            qa[mt][kc][1] = f2tf32(p1[kc * 8] * QSCALE);
            qa[mt][kc][2] = f2tf32(p0[kc * 8 + 4] * QSCALE);
            qa[mt][kc][3] = f2tf32(p1[kc * 8 + 4] * QSCALE);
        }
    }

    float o[2][8][4];
#pragma unroll
    for (int mt = 0; mt < 2; mt++)
#pragma unroll
        for (int nc = 0; nc < 8; nc++)
#pragma unroll
            for (int e = 0; e < 4; e++) o[mt][nc][e] = 0.f;
    float mA[2] = {-1e30f, -1e30f}, mB[2] = {-1e30f, -1e30f};
    float lA[2] = {0.f, 0.f}, lB[2] = {0.f, 0.f};

    // loader mappings
    const int kkey = tid >> 1;               // K row 0..63
    const int kc0 = (tid & 1) * 32;          // 32-col half
    const int vpr = tid >> 2;                // 0..31 row-pairs
    const int vkb = vpr >> 2, vq = vpr & 3;
    const int vr0 = vkb * 8 + vq;            // V rows vr0, vr0+4
    const int vcs = (tid & 3) * 16;          // 16-col group

    for (int kt = 0; kt < SEQ / 64; kt++) {
        // ---- K tile load + pack ----
        {
            const float* kg = qkv + base + (size_t)(kt * 64 + kkey) * QKV_DIM
                              + DIM + h * HEAD_DIM + kc0;
            float kf[32];
#pragma unroll
            for (int i = 0; i < 8; i++) {
                float4 t = *(const float4*)(kg + i * 4);
                kf[i * 4 + 0] = t.x; kf[i * 4 + 1] = t.y;
                kf[i * 4 + 2] = t.z; kf[i * 4 + 3] = t.w;
            }
#pragma unroll
            for (int kb = 0; kb < 4; kb++)
#pragma unroll
                for (int qq = 0; qq < 4; qq++) {
                    uint2 t;
                    t.x = f2tf32(kf[kb * 8 + qq]);
                    t.y = f2tf32(kf[kb * 8 + qq + 4]);
                    *(uint2*)&ks2[kkey * KS + kc0 + kb * 8 + qq * 2] = t;
                }
        }
        // ---- V tile load + pack (row-pairs kr, kr+4) ----
        {
            const float* vgl = qkv + base + (size_t)(kt * 64 + vr0) * QKV_DIM
                               + 2 * DIM + h * HEAD_DIM + vcs;
            const float* vgh = vgl + (size_t)4 * QKV_DIM;
            float vlo[16], vhi[16];
#pragma unroll
            for (int i = 0; i < 4; i++) {
                float4 a = *(const float4*)(vgl + i * 4);
                float4 c = *(const float4*)(vgh + i * 4);
                vlo[i * 4 + 0] = a.x; vlo[i * 4 + 1] = a.y;
                vlo[i * 4 + 2] = a.z; vlo[i * 4 + 3] = a.w;
                vhi[i * 4 + 0] = c.x; vhi[i * 4 + 1] = c.y;
                vhi[i * 4 + 2] = c.z; vhi[i * 4 + 3] = c.w;
            }
#pragma unroll
            for (int i = 0; i < 16; i++) {
                uint2 t;
                t.x = f2tf32(vlo[i]);
                t.y = f2tf32(vhi[i]);
                *(uint2*)&vp[(vcs + i) * KS + vkb * 8 + vq * 2] = t;
            }
        }
        __syncthreads();

        // ---- S = Q*K^T (32x64 per warp) ----
        float sc[2][8][4];
#pragma unroll
        for (int nc = 0; nc < 8; nc++) {
#pragma unroll
            for (int e = 0; e < 4; e++) { sc[0][nc][e] = 0.f; sc[1][nc][e] = 0.f; }
            const int key = nc * 8 + r0;
#pragma unroll
            for (int kc = 0; kc < 8; kc++) {
                uint2 kk = *(const uint2*)&ks2[key * KS + kc * 8 + q4 * 2];
                mma_tf32(sc[0][nc], qa[0][kc], kk.x, kk.y);
                mma_tf32(sc[1][nc], qa[1][kc], kk.x, kk.y);
            }
        }

        // ---- online softmax (exp2 domain) + P store ----
#pragma unroll
        for (int mt = 0; mt < 2; mt++) {
            float tA = -1e30f, tB = -1e30f;
#pragma unroll
            for (int nc = 0; nc < 8; nc++) {
                tA = fmaxf(tA, fmaxf(sc[mt][nc][0], sc[mt][nc][1]));
                tB = fmaxf(tB, fmaxf(sc[mt][nc][2], sc[mt][nc][3]));
            }
            tA = fmaxf(tA, __shfl_xor_sync(0xffffffffu, tA, 1));
            tA = fmaxf(tA, __shfl_xor_sync(0xffffffffu, tA, 2));
            tB = fmaxf(tB, __shfl_xor_sync(0xffffffffu, tB, 1));
            tB = fmaxf(tB, __shfl_xor_sync(0xffffffffu, tB, 2));
            const float mnA = fmaxf(mA[mt], tA);
            const float mnB = fmaxf(mB[mt], tB);
            const float cA = ex2(mA[mt] - mnA);
            const float cB = ex2(mB[mt] - mnB);
            mA[mt] = mnA; mB[mt] = mnB;
            lA[mt] *= cA; lB[mt] *= cB;
#pragma unroll
            for (int nc = 0; nc < 8; nc++) {
                o[mt][nc][0] *= cA; o[mt][nc][1] *= cA;
                o[mt][nc][2] *= cB; o[mt][nc][3] *= cB;
                const float p0 = ex2(sc[mt][nc][0] - mnA);
                const float p1 = ex2(sc[mt][nc][1] - mnA);
                const float p2 = ex2(sc[mt][nc][2] - mnB);
                const float p3 = ex2(sc[mt][nc][3] - mnB);
                lA[mt] += p0 + p1; lB[mt] += p2 + p3;
                uint4 st;
                st.x = f2tf32(p0); st.y = f2tf32(p2);
                st.z = f2tf32(p1); st.w = f2tf32(p3);
                *(uint4*)&pw[(mt * 8 + r0) * PS + (nc * 8 + 2 * q4) * 2] = st;
            }
        }
        __syncwarp();

        // ---- O += P*V ----
#pragma unroll
        for (int kb = 0; kb < 8; kb++) {
            unsigned af[2][4];
#pragma unroll
            for (int mt = 0; mt < 2; mt++) {
                const unsigned* pr = &pw[(mt * 8 + r0) * PS + (kb * 8 + q4) * 2];
                uint2 a0 = *(const uint2*)pr;
                uint2 a1 = *(const uint2*)(pr + 8);
                af[mt][0] = a0.x; af[mt][1] = a0.y;
                af[mt][2] = a1.x; af[mt][3] = a1.y;
            }
#pragma unroll
            for (int nc = 0; nc < 8; nc++) {
                uint2 vv = *(const uint2*)&vp[(nc * 8 + r0) * KS + kb * 8 + q4 * 2];
                mma_tf32(o[0][nc], af[0], vv.x, vv.y);
                mma_tf32(o[1][nc], af[1], vv.x, vv.y);
            }
        }
        __syncthreads();
    }

    // ---- epilogue ----
#pragma unroll
    for (int mt = 0; mt < 2; mt++) {
        float la = lA[mt], lb = lB[mt];
        la += __shfl_xor_sync(0xffffffffu, la, 1);
        la += __shfl_xor_sync(0xffffffffu, la, 2);
        lb += __shfl_xor_sync(0xffffffffu, lb, 1);
        lb += __shfl_xor_sync(0xffffffffu, lb, 2);
        const float ia = 1.f / la, ib = 1.f / lb;
        const int row = qt * 128 + wid * 32 + mt * 16 + r0;
        float* oA = out + ((size_t)b * SEQ + row) * DIM + h * HEAD_DIM;
        float* oB = oA + (size_t)8 * DIM;
#pragma unroll
        for (int nc = 0; nc < 8; nc++) {
            const int col = nc * 8 + 2 * q4;
            *(float2*)(oA + col) = make_float2(o[mt][nc][0] * ia, o[mt][nc][1] * ia);
            *(float2*)(oB + col) = make_float2(o[mt][nc][2] * ib, o[mt][nc][3] * ib);
        }
    }
}

// ===========================================================================
extern "C" void kernel_launch(void* const* d_in, const int* in_sizes, int n_in,
                              void* d_out, int out_size) {
    const float* x      = (const float*)d_in[0];
    const float* w_qkv  = (const float*)d_in[1];
    const float* b_qkv  = (const float*)d_in[2];
    const float* w_proj = (const float*)d_in[3];
    const float* b_proj = (const float*)d_in[4];
    float* out = (float*)d_out;

    float* qkv = nullptr;
    float* att = nullptr;
    cudaGetSymbolAddress((void**)&qkv, g_qkv);
    cudaGetSymbolAddress((void**)&att, g_att);

    const int M = BATCH * SEQ;                 // 8192
    const int GEMM_SMEM = 2 * G_BUF * 4;       // 58368 B
    const int FA_SMEM = F_WORDS * 4;           // 71680 B

    static int configured = 0;
    cudaFuncSetAttribute(gemm_tf32_v3, cudaFuncAttributeMaxDynamicSharedMemorySize,
                         GEMM_SMEM);
    cudaFuncSetAttribute(flash_tf32_v3, cudaFuncAttributeMaxDynamicSharedMemorySize,
                         FA_SMEM);
    (void)configured;

    {
        dim3 grid(QKV_DIM / 128, M / 128);     // (18, 64)
        gemm_tf32_v3<<<grid, 128, GEMM_SMEM>>>(x, w_qkv, b_qkv, qkv, M, QKV_DIM, DIM);
    }
    {
        dim3 grid(SEQ / 128, HEADS, BATCH);    // (16, 12, 4)
        flash_tf32_v3<<<grid, 128, FA_SMEM>>>(qkv, att);
    }
    {
        dim3 grid(DIM / 128, M / 128);         // (6, 64)
        gemm_tf32_v3<<<grid, 128, GEMM_SMEM>>>(att, w_proj, b_proj, out, M, DIM, DIM);
    }
}